// round 17
// baseline (speedup 1.0000x reference)
#include <cuda_runtime.h>
#include <cuda_bf16.h>
#include <math.h>
#include <stdint.h>

#define BATCH 2
#define SEQ   2048
#define DMODEL 1024
#define NHEAD 16
#define DK    64
#define SCALE 0.35355339059327376f
#define M_TOT (BATCH * SEQ)

// scratch
__device__ float g_q[BATCH * NHEAD * SEQ * DK];
__device__ float g_k[BATCH * NHEAD * SEQ * DK];
__device__ float g_v[BATCH * NHEAD * SEQ * DK];
__device__ float g_attn[BATCH * SEQ * DMODEL];    // tf32-rounded, k-paired by attn epilogue? (no: natural; proj_o A input repacked below)
__device__ float g_rx[3 * M_TOT * DMODEL];        // rounded + k-paired query/key/value
__device__ float g_rw[4 * DMODEL * DMODEL];       // rounded + k-paired weights
__device__ float g_ra[M_TOT * DMODEL];            // rounded + k-paired attn output (for proj_o)

__device__ __forceinline__ uint32_t f2tf(float f) {
    uint32_t u; asm("cvt.rna.tf32.f32 %0, %1;" : "=r"(u) : "f"(f)); return u;
}
__device__ __forceinline__ uint32_t smem_u32(const void* p) {
    uint32_t a;
    asm("{ .reg .u64 t; cvta.to.shared.u64 t, %1; cvt.u32.u64 %0, t; }" : "=r"(a) : "l"(p));
    return a;
}
__device__ __forceinline__ void mma_hw(float* c, const uint32_t* a, const uint32_t* b) {
    asm volatile(
        "mma.sync.aligned.m16n8k8.row.col.f32.tf32.tf32.f32 "
        "{%0,%1,%2,%3}, {%4,%5,%6,%7}, {%8,%9}, {%0,%1,%2,%3};\n"
        : "+f"(c[0]), "+f"(c[1]), "+f"(c[2]), "+f"(c[3])
        : "r"(a[0]), "r"(a[1]), "r"(a[2]), "r"(a[3]), "r"(b[0]), "r"(b[1]));
}

#define CP16(dst, src) asm volatile("cp.async.cg.shared.global [%0], [%1], 16;" :: "r"(dst), "l"(src) : "memory")
#define CP_COMMIT()    asm volatile("cp.async.commit_group;" ::: "memory")
#define CP_WAIT1()     asm volatile("cp.async.wait_group 1;" ::: "memory")
#define CP_WAIT0()     asm volatile("cp.async.wait_group 0;" ::: "memory")

__device__ __forceinline__ int colperm(int dk) {
    return (dk & ~7) + ((dk & 3) << 1) + ((dk >> 2) & 1);
}

// ---------------- tf32 pre-round + k-pair interleave -----------------------
// out 8-group = {in0,in4,in1,in5,in2,in6,in3,in7}  (colperm on k index)
#define NI8 ((M_TOT * DMODEL) / 8)       // 8-groups per input tensor
#define NW8 ((DMODEL * DMODEL) / 8)
__device__ __forceinline__ void pair8(const float4* s, float4* d, int j) {
    float4 a = s[2 * j], b = s[2 * j + 1];
    float4 o0, o1;
    o0.x = __uint_as_float(f2tf(a.x)); o0.y = __uint_as_float(f2tf(b.x));
    o0.z = __uint_as_float(f2tf(a.y)); o0.w = __uint_as_float(f2tf(b.y));
    o1.x = __uint_as_float(f2tf(a.z)); o1.y = __uint_as_float(f2tf(b.z));
    o1.z = __uint_as_float(f2tf(a.w)); o1.w = __uint_as_float(f2tf(b.w));
    d[2 * j] = o0; d[2 * j + 1] = o1;
}
__global__ __launch_bounds__(256) void preround(
    const float4* __restrict__ x0, const float4* __restrict__ x1, const float4* __restrict__ x2,
    const float4* __restrict__ w0, const float4* __restrict__ w1,
    const float4* __restrict__ w2, const float4* __restrict__ w3,
    float4* __restrict__ ox, float4* __restrict__ ow)
{
    const int total = 3 * NI8 + 4 * NW8;
    for (int i = blockIdx.x * blockDim.x + threadIdx.x; i < total;
         i += gridDim.x * blockDim.x) {
        if (i < 3 * NI8) {
            int t = i / NI8, j = i - t * NI8;
            const float4* s = (t == 0) ? x0 : (t == 1) ? x1 : x2;
            pair8(s, ox + (size_t)t * 2 * NI8, j);
        } else {
            int i2 = i - 3 * NI8;
            int t = i2 / NW8, j = i2 - t * NW8;
            const float4* s = (t == 0) ? w0 : (t == 1) ? w1 : (t == 2) ? w2 : w3;
            pair8(s, ow + (size_t)t * 2 * NW8, j);
        }
    }
}
// repack attn output (already tf32-rounded) into k-paired layout for proj_o
__global__ __launch_bounds__(256) void pair_attn(
    const float4* __restrict__ in, float4* __restrict__ outp)
{
    for (int j = blockIdx.x * blockDim.x + threadIdx.x; j < NI8;
         j += gridDim.x * blockDim.x) {
        float4 a = in[2 * j], b = in[2 * j + 1];
        float4 o0 = make_float4(a.x, b.x, a.y, b.y);
        float4 o1 = make_float4(a.z, b.z, a.w, b.w);
        outp[2 * j] = o0; outp[2 * j + 1] = o1;
    }
}

// ---------------- projection GEMM: k-paired operands, LDS.64 frags ---------
#define PPAD 40
#define PBUF (128 * PPAD)
#define PROJ_SMEM (4 * PBUF * 4)          // 81920 bytes

__device__ __forceinline__ void proj_body(
    float* Asr, float* Bsr, uint32_t sbA, uint32_t sbB,
    const float* __restrict__ X, const float* __restrict__ W,
    float* __restrict__ out, int mode, float scale, int bx, int by)
{
    const int tid = threadIdx.x, lane = tid & 31, warp = tid >> 5;
    const int wm = warp >> 1, wn = warp & 1, gr = lane >> 2, gc = lane & 3;
    const int m0 = by * 128, n0 = bx * 128;
    float acc[2][8][4] = {};

#pragma unroll
    for (int j = 0; j < 4; j++) {
        int c = tid + 256 * j;
        int r = c >> 3, c4 = (c & 7) * 4;
        CP16(sbA + (r * PPAD + c4) * 4, &X[(size_t)(m0 + r) * DMODEL + c4]);
        CP16(sbB + (r * PPAD + c4) * 4, &W[(size_t)(n0 + r) * DMODEL + c4]);
    }
    CP_COMMIT();

    for (int it = 0; it < 32; it++) {
        const int buf = it & 1;
        if (it + 1 < 32) {
            const int nb = (it + 1) & 1;
            const int k0 = (it + 1) * 32;
#pragma unroll
            for (int j = 0; j < 4; j++) {
                int c = tid + 256 * j;
                int r = c >> 3, c4 = (c & 7) * 4;
                CP16(sbA + (nb * 2 * PBUF + r * PPAD + c4) * 4,
                     &X[(size_t)(m0 + r) * DMODEL + k0 + c4]);
                CP16(sbB + (nb * 2 * PBUF + r * PPAD + c4) * 4,
                     &W[(size_t)(n0 + r) * DMODEL + k0 + c4]);
            }
            CP_COMMIT();
            CP_WAIT1();
        } else {
            CP_WAIT0();
        }
        __syncthreads();

        const uint2* As2 = (const uint2*)(Asr + buf * 2 * PBUF);
        const uint2* Bs2 = (const uint2*)(Bsr + buf * 2 * PBUF);
#pragma unroll
        for (int kk = 0; kk < 32; kk += 8) {
            uint32_t afr[2][4], bfr[8][2];
#pragma unroll
            for (int mt = 0; mt < 2; mt++) {
                int rm = wm * 32 + mt * 16;
                uint2 a0 = As2[((rm + gr) * PPAD + kk) / 2 + gc];
                uint2 a1 = As2[((rm + 8 + gr) * PPAD + kk) / 2 + gc];
                afr[mt][0] = a0.x; afr[mt][1] = a1.x;
                afr[mt][2] = a0.y; afr[mt][3] = a1.y;
            }
#pragma unroll
            for (int nt = 0; nt < 8; nt++) {
                int cn = wn * 64 + nt * 8;
                uint2 b = Bs2[((cn + gr) * PPAD + kk) / 2 + gc];
                bfr[nt][0] = b.x; bfr[nt][1] = b.y;
            }
#pragma unroll
            for (int mt = 0; mt < 2; mt++)
#pragma unroll
                for (int nt = 0; nt < 8; nt++)
                    mma_hw(acc[mt][nt], afr[mt], bfr[nt]);
        }
        __syncthreads();
    }

#pragma unroll
    for (int mt = 0; mt < 2; mt++)
#pragma unroll
        for (int nt = 0; nt < 8; nt++)
#pragma unroll
            for (int half = 0; half < 2; half++) {
                int m = m0 + wm * 32 + mt * 16 + gr + half * 8;
                int n = n0 + wn * 64 + nt * 8 + gc * 2;
                float v0 = acc[mt][nt][half * 2 + 0] * scale;
                float v1 = acc[mt][nt][half * 2 + 1] * scale;
                if (mode == 0) {
                    *(float2*)(out + (size_t)m * DMODEL + n) = make_float2(v0, v1);
                } else {
                    int b = m >> 11, l = m & 2047, hh = n >> 6, dk = n & 63;
                    size_t base = ((size_t)b * NHEAD + hh) * SEQ * DK;
                    if (mode == 1) {
                        float* dst = out + base + (size_t)l * DK;
                        dst[colperm(dk)]     = __uint_as_float(f2tf(v0));
                        dst[colperm(dk + 1)] = __uint_as_float(f2tf(v1));
                    } else {
                        int tile = l >> 6, t = l & 63;
                        int kp = ((t >> 3) << 2) + (t & 3), hp = (t >> 2) & 1;
                        float* dst = out + base + (size_t)tile * 4096 + ((kp << 6) + dk) * 2 + hp;
                        dst[0] = __uint_as_float(f2tf(v0));
                        dst[2] = __uint_as_float(f2tf(v1));
                    }
                }
            }
}

__global__ __launch_bounds__(256, 2) void proj_qkv(
    const float* __restrict__ Xr, const float* __restrict__ Wr,
    float* __restrict__ oq, float* __restrict__ ok, float* __restrict__ ov)
{
    extern __shared__ float psm[];
    float* Asr = psm;
    float* Bsr = psm + PBUF;
    const int z = blockIdx.z;
    const float* X = Xr + (size_t)z * (M_TOT * DMODEL);
    const float* W = Wr + (size_t)z * (DMODEL * DMODEL);
    float* out     = (z == 0) ? oq : (z == 1) ? ok : ov;
    proj_body(Asr, Bsr, smem_u32(Asr), smem_u32(Bsr), X, W, out,
              (z == 2) ? 2 : 1, (z == 2) ? 1.0f : SCALE, blockIdx.x, blockIdx.y);
}

__global__ __launch_bounds__(256, 2) void proj_o(
    const float* __restrict__ X, const float* __restrict__ W, float* __restrict__ out)
{
    extern __shared__ float psm[];
    float* Asr = psm;
    float* Bsr = psm + PBUF;
    proj_body(Asr, Bsr, smem_u32(Asr), smem_u32(Bsr), X, W, out, 0, 1.0f,
              blockIdx.x, blockIdx.y);
}

// ---------------- flash attention (R14 best: static-shift softmax) ---------
#define KSTR 72
#define PSTR 68
#define VSTR 136
#define K0F  0
#define K1F  (64 * KSTR)
#define V0F  (2 * 64 * KSTR)
#define V1F  (2 * 64 * KSTR + 32 * VSTR)
#define SMEM_ATT ((2 * 64 * KSTR + 2 * 32 * VSTR) * 4)   // 71680 bytes
#define SHIFT 8.0f

__global__ __launch_bounds__(128, 3) void attn_cp(
    const float* __restrict__ q, const float* __restrict__ k,
    const float* __restrict__ v, const float* __restrict__ pb,
    float* __restrict__ out)
{
    extern __shared__ float smf[];
    const uint32_t sb = smem_u32(smf);
    const int tid = threadIdx.x, lane = tid & 31, warp = tid >> 5;
    const int gr = lane >> 2, gc = lane & 3;
    const int bh = blockIdx.y, qb = blockIdx.x * 64;

    uint32_t qa[8][4];
    {
        const float* qg = q + ((size_t)bh * SEQ + qb + warp * 16) * DK;
#pragma unroll
        for (int ks = 0; ks < 8; ks++) {
            uint2 t0 = *(const uint2*)&qg[(size_t)gr * DK + ks * 8 + gc * 2];
            uint2 t1 = *(const uint2*)&qg[(size_t)(gr + 8) * DK + ks * 8 + gc * 2];
            qa[ks][0] = t0.x; qa[ks][2] = t0.y;
            qa[ks][1] = t1.x; qa[ks][3] = t1.y;
        }
    }

    float lrow[2] = {0.f, 0.f};
    float oacc[8][4] = {};

    const float* kbase = k + (size_t)bh * SEQ * DK;
    const float* vbase = v + (size_t)bh * SEQ * DK;
    const float* pbbase = pb + ((size_t)bh * SEQ + qb + warp * 16) * SEQ;

    {
        const float4* kg = (const float4*)kbase;
        const float4* vg = (const float4*)vbase;
#pragma unroll
        for (int j = 0; j < 8; j++) {
            int c = tid + 128 * j;
            CP16(sb + (K0F + (c >> 4) * KSTR + (c & 15) * 4) * 4, kg + c);
            CP16(sb + (V0F + (c >> 5) * VSTR + (c & 31) * 4) * 4, vg + c);
        }
        CP_COMMIT();
    }

    for (int kt = 0; kt < SEQ / 64; kt++) {
        const int cur = kt & 1;
        const int kb = kt * 64;

        if (kt + 1 < SEQ / 64) {
            const float4* kg = (const float4*)(kbase + (size_t)(kb + 64) * DK);
            const float4* vg = (const float4*)(vbase + (size_t)(kt + 1) * 4096);
            const int kf = cur ? K0F : K1F;
            const int vf = cur ? V0F : V1F;
#pragma unroll
            for (int j = 0; j < 8; j++) {
                int c = tid + 128 * j;
                CP16(sb + (kf + (c >> 4) * KSTR + (c & 15) * 4) * 4, kg + c);
                CP16(sb + (vf + (c >> 5) * VSTR + (c & 31) * 4) * 4, vg + c);
            }
            CP_COMMIT();
        }

        float2 pbv[16];
#pragma unroll
        for (int nt = 0; nt < 8; nt++) {
            pbv[nt]     = *(const float2*)&pbbase[(size_t)gr * SEQ + kb + nt * 8 + gc * 2];
            pbv[8 + nt] = *(const float2*)&pbbase[(size_t)(gr + 8) * SEQ + kb + nt * 8 + gc * 2];
        }

        if (kt + 1 < SEQ / 64) { CP_WAIT1(); } else { CP_WAIT0(); }
        __syncthreads();

        const float* Kc = smf + (cur ? K1F : K0F);
        const float* Vc = smf + (cur ? V1F : V0F);

        float sacc[8][4] = {};
#pragma unroll
        for (int ks = 0; ks < 8; ks++) {
#pragma unroll
            for (int nt = 0; nt < 8; nt++) {
                uint2 b = *(const uint2*)&Kc[(nt * 8 + gr) * KSTR + ks * 8 + gc * 2];
                uint32_t bfr[2] = { b.x, b.y };
                mma_hw(sacc[nt], qa[ks], bfr);
            }
        }
        __syncthreads();

#pragma unroll
        for (int r = 0; r < 2; r++) {
            float rs = 0.f;
#pragma unroll
            for (int nt = 0; nt < 8; nt++) {
                float b0 = (r == 0) ? pbv[nt].x : pbv[8 + nt].x;
                float b1 = (r == 0) ? pbv[nt].y : pbv[8 + nt].y;
                sacc[nt][r * 2]     = __expf(sacc[nt][r * 2]     + b0 - SHIFT);
                sacc[nt][r * 2 + 1] = __expf(sacc[nt][r * 2 + 1] + b1 - SHIFT);
                rs += sacc[nt][r * 2] + sacc[nt][r * 2 + 1];
            }
            rs += __shfl_xor_sync(0xffffffffu, rs, 1);
            rs += __shfl_xor_sync(0xffffffffu, rs, 2);
            lrow[r] += rs;
        }

        {
            float* Pc = (float*)Kc;
            int rm = warp * 16;
#pragma unroll
            for (int nt = 0; nt < 8; nt++) {
                *(uint2*)&Pc[(rm + gr) * PSTR + nt * 8 + gc * 2] =
                    make_uint2(f2tf(sacc[nt][0]), f2tf(sacc[nt][1]));
                *(uint2*)&Pc[(rm + 8 + gr) * PSTR + nt * 8 + gc * 2] =
                    make_uint2(f2tf(sacc[nt][2]), f2tf(sacc[nt][3]));
            }
        }
        __syncwarp();

        {
            const float* Pc = Kc;
            int rm = warp * 16;
#pragma unroll
            for (int ks = 0; ks < 8; ks++) {
                uint32_t pa[4];
                pa[0] = __float_as_uint(Pc[(rm + gr) * PSTR + ks * 8 + gc]);
                pa[1] = __float_as_uint(Pc[(rm + 8 + gr) * PSTR + ks * 8 + gc]);
                pa[2] = __float_as_uint(Pc[(rm + gr) * PSTR + ks * 8 + 4 + gc]);
                pa[3] = __float_as_uint(Pc[(rm + 8 + gr) * PSTR + ks * 8 + 4 + gc]);
#pragma unroll
                for (int dt = 0; dt < 8; dt++) {
                    uint2 b = *(const uint2*)&Vc[(ks * 4 + gc) * VSTR + (dt * 8 + gr) * 2];
                    uint32_t bfr[2] = { b.x, b.y };
                    mma_hw(oacc[dt], pa, bfr);
                }
            }
        }
        __syncthreads();
    }

    // epilogue: normalized + tf32-rounded (natural layout; pair_attn repacks)
    const int b = bh >> 4, h = bh & 15;
    float inv0 = 1.f / lrow[0];
    float inv1 = 1.f / lrow[1];
    float* dst = out + ((size_t)b * SEQ + qb + warp * 16) * DMODEL + h * DK;
#pragma unroll
    for (int dt = 0; dt < 8; dt++) {
        *(uint2*)&dst[(size_t)gr * DMODEL + dt * 8 + gc * 2] =
            make_uint2(f2tf(oacc[dt][0] * inv0), f2tf(oacc[dt][1] * inv0));
        *(uint2*)&dst[(size_t)(gr + 8) * DMODEL + dt * 8 + gc * 2] =
            make_uint2(f2tf(oacc[dt][2] * inv1), f2tf(oacc[dt][3] * inv1));
    }
}

// ---------------- launch ----------------------------------------------------
extern "C" void kernel_launch(void* const* d_in, const int* in_sizes, int n_in,
                              void* d_out, int out_size)
{
    const float* query = (const float*)d_in[0];
    const float* key   = (const float*)d_in[1];
    const float* value = (const float*)d_in[2];
    const float* pbias = (const float*)d_in[3];
    const float* Wq    = (const float*)d_in[4];
    const float* Wk    = (const float*)d_in[5];
    const float* Wv    = (const float*)d_in[6];
    const float* Wo    = (const float*)d_in[7];
    float* out = (float*)d_out;

    float *qp, *kp, *vp, *ap, *rx, *rw, *ra;
    cudaGetSymbolAddress((void**)&qp, g_q);
    cudaGetSymbolAddress((void**)&kp, g_k);
    cudaGetSymbolAddress((void**)&vp, g_v);
    cudaGetSymbolAddress((void**)&ap, g_attn);
    cudaGetSymbolAddress((void**)&rx, g_rx);
    cudaGetSymbolAddress((void**)&rw, g_rw);
    cudaGetSymbolAddress((void**)&ra, g_ra);

    cudaFuncSetAttribute(attn_cp, cudaFuncAttributeMaxDynamicSharedMemorySize, SMEM_ATT);
    cudaFuncSetAttribute(proj_qkv, cudaFuncAttributeMaxDynamicSharedMemorySize, PROJ_SMEM);
    cudaFuncSetAttribute(proj_o,   cudaFuncAttributeMaxDynamicSharedMemorySize, PROJ_SMEM);

    preround<<<2048, 256>>>(
        (const float4*)query, (const float4*)key, (const float4*)value,
        (const float4*)Wq, (const float4*)Wk, (const float4*)Wv, (const float4*)Wo,
        (float4*)rx, (float4*)rw);

    dim3 qkvgrid(DMODEL / 128, M_TOT / 128, 3);
    proj_qkv<<<qkvgrid, 256, PROJ_SMEM>>>(rx, rw, qp, kp, vp);

    dim3 agrid(SEQ / 64, BATCH * NHEAD);
    attn_cp<<<agrid, 128, SMEM_ATT>>>(qp, kp, vp, pbias, ap);

    pair_attn<<<1024, 256>>>((const float4*)ap, (float4*)ra);

    dim3 ogrid(DMODEL / 128, M_TOT / 128);
    proj_o<<<ogrid, 256, PROJ_SMEM>>>(ra, rw + 3 * (size_t)DMODEL * DMODEL, out);
}